// round 3
// baseline (speedup 1.0000x reference)
#include <cuda_runtime.h>
#include <cstdint>

#define N_NODES 50000
#define N_EDGES 800000
#define D_IN 64
#define D_OUT 64
#define E_DIM 32
#define BN_EPS 1e-5f

// ---------------- scratch (static device memory; 16B aligned for float4) -------
__device__ __align__(16) float g_aggX[N_NODES * D_IN];   // sum of x[src] per node
__device__ __align__(16) float g_aggE[N_NODES * E_DIM];  // sum of edge_attr per node
__device__ __align__(16) float g_deg[N_NODES];           // degree (float)
__device__ __align__(16) float g_h[N_NODES * D_OUT];     // pre-BN hidden
__device__ __align__(16) float g_sum[D_OUT];
__device__ __align__(16) float g_sumsq[D_OUT];
__device__ __align__(16) float g_C1[E_DIM * D_OUT];      // We @ W1
__device__ __align__(16) float g_c2[D_OUT];              // be @ W1
__device__ __align__(16) float g_scale[D_OUT];           // gamma * rstd
__device__ __align__(16) float g_shift[D_OUT];           // beta - mean * scale

// ---------------- kernel 0: zero accumulators ----------------
__global__ void zero_kernel() {
    int idx = blockIdx.x * blockDim.x + threadIdx.x;
    int stride = gridDim.x * blockDim.x;
    float4 z = make_float4(0.f, 0.f, 0.f, 0.f);
    for (int i = idx; i < N_NODES * (D_IN / 4); i += stride) ((float4*)g_aggX)[i] = z;
    for (int i = idx; i < N_NODES * (E_DIM / 4); i += stride) ((float4*)g_aggE)[i] = z;
    for (int i = idx; i < N_NODES; i += stride) g_deg[i] = 0.f;
    if (idx < D_OUT) { g_sum[idx] = 0.f; g_sumsq[idx] = 0.f; }
}

// ---------------- kernel 1: precompute C1 = We@W1, c2 = be@W1 ----------------
__global__ void prep_kernel(const float* __restrict__ We,
                            const float* __restrict__ be,
                            const float* __restrict__ W1) {
    int tid = threadIdx.x;
    for (int idx = tid; idx < E_DIM * D_OUT; idx += blockDim.x) {
        int k = idx >> 6, d = idx & 63;
        float s = 0.f;
        #pragma unroll 8
        for (int m = 0; m < D_IN; m++) s += We[k * D_IN + m] * W1[m * D_OUT + d];
        g_C1[idx] = s;
    }
    if (tid < D_OUT) {
        float s = 0.f;
        #pragma unroll 8
        for (int m = 0; m < D_IN; m++) s += be[m] * W1[m * D_OUT + tid];
        g_c2[tid] = s;
    }
}

// ---------------- kernel 2: edge scatter (vector float4 atomics) ----------------
// Each warp handles 2 edges. Lanes 0-15: x[src] of edge0 (float4 each);
// lanes 16-31: x[src] of edge1. Then lanes 0-7 / 8-15 scatter edge_attr of
// edge0 / edge1; lanes 16,17 bump degree counters.
// edge_index arrives as int32 (harness converts int64 -> int32).
__global__ void edge_kernel(const float4* __restrict__ x4,
                            const int* __restrict__ ei,
                            const float4* __restrict__ ea4) {
    int gwarp = (blockIdx.x * blockDim.x + threadIdx.x) >> 5;
    int lane = threadIdx.x & 31;
    int e0 = gwarp * 2;
    if (e0 >= N_EDGES) return;

    int half = lane >> 4, li = lane & 15;
    int e = e0 + half;
    bool v = (e < N_EDGES);
    int src = 0, dst = 0;
    if (v) {
        src = __ldg(&ei[e]);
        dst = __ldg(&ei[N_EDGES + e]);
    }
    // scatter x[src] -> aggX[dst]
    if (v) {
        float4 xv = __ldg(&x4[(size_t)src * (D_IN / 4) + li]);
        atomicAdd(((float4*)(g_aggX + (size_t)dst * D_IN)) + li, xv);
    }
    // broadcast both dsts to the whole warp
    int dA = __shfl_sync(0xffffffffu, dst, 0);
    int dB = __shfl_sync(0xffffffffu, dst, 16);
    // scatter edge_attr
    if (lane < 16) {
        int e2 = e0 + (lane >> 3);
        if (e2 < N_EDGES) {
            int d2 = (lane < 8) ? dA : dB;
            int lj = lane & 7;
            float4 av = __ldg(&ea4[(size_t)e2 * (E_DIM / 4) + lj]);
            atomicAdd(((float4*)(g_aggE + (size_t)d2 * E_DIM)) + lj, av);
        }
    } else if (lane < 18) {
        int e3 = e0 + (lane - 16);
        if (e3 < N_EDGES) atomicAdd(&g_deg[(lane == 16) ? dA : dB], 1.f);
    }
}

// ---------------- kernel 3: h = (aggX+x)@W1 + aggE@C1 + deg*c2 + b1; + stats ----
// 8 warps/block, 4 rows/warp per iteration (amortizes weight LDS 4x).
// Lane owns output dims d and d+32.
__global__ void node_h_kernel(const float* __restrict__ x,
                              const float* __restrict__ W1,
                              const float* __restrict__ b1) {
    __shared__ __align__(16) float W1s[D_IN * D_OUT];
    __shared__ __align__(16) float C1s[E_DIM * D_OUT];
    __shared__ float c2s[D_OUT], b1s[D_OUT];
    __shared__ __align__(16) float rv[8][4][D_IN];
    __shared__ __align__(16) float ra[8][4][E_DIM];
    __shared__ float bsum[D_OUT], bsq[D_OUT];

    int tid = threadIdx.x;
    for (int i = tid; i < D_IN * D_OUT; i += 256) W1s[i] = W1[i];
    for (int i = tid; i < E_DIM * D_OUT; i += 256) C1s[i] = g_C1[i];
    if (tid < D_OUT) { c2s[tid] = g_c2[tid]; b1s[tid] = b1[tid]; bsum[tid] = 0.f; bsq[tid] = 0.f; }
    __syncthreads();

    int warp = tid >> 5, lane = tid & 31;
    int d = lane;
    float s0 = 0.f, s1 = 0.f, q0 = 0.f, q1 = 0.f;

    int nGroups = (N_NODES + 31) / 32;
    for (int g = blockIdx.x; g < nGroups; g += gridDim.x) {
        int rowBase = g * 32 + warp * 4;
        // stage 4 rows: v = aggX + x  (GIN_EPS=0), and aggE
        #pragma unroll
        for (int r = 0; r < 4; r++) {
            int row = rowBase + r;
            if (row < N_NODES) {
                if (lane < 16) {
                    float4 a = ((const float4*)g_aggX)[row * 16 + lane];
                    float4 xv = ((const float4*)x)[row * 16 + lane];
                    a.x += xv.x; a.y += xv.y; a.z += xv.z; a.w += xv.w;
                    ((float4*)&rv[warp][r][0])[lane] = a;
                } else if (lane < 24) {
                    int lj = lane - 16;
                    ((float4*)&ra[warp][r][0])[lj] = ((const float4*)g_aggE)[row * 8 + lj];
                }
            }
        }
        __syncwarp();

        float h[4][2];
        #pragma unroll
        for (int r = 0; r < 4; r++) {
            int row = rowBase + r;
            float dg = (row < N_NODES) ? g_deg[row] : 0.f;
            h[r][0] = dg * c2s[d] + b1s[d];
            h[r][1] = dg * c2s[d + 32] + b1s[d + 32];
        }
        #pragma unroll 8
        for (int k = 0; k < D_IN; k++) {
            float w0 = W1s[k * D_OUT + d];
            float w1 = W1s[k * D_OUT + d + 32];
            #pragma unroll
            for (int r = 0; r < 4; r++) {
                float a = rv[warp][r][k];
                h[r][0] += a * w0; h[r][1] += a * w1;
            }
        }
        #pragma unroll 8
        for (int k = 0; k < E_DIM; k++) {
            float w0 = C1s[k * D_OUT + d];
            float w1 = C1s[k * D_OUT + d + 32];
            #pragma unroll
            for (int r = 0; r < 4; r++) {
                float a = ra[warp][r][k];
                h[r][0] += a * w0; h[r][1] += a * w1;
            }
        }
        #pragma unroll
        for (int r = 0; r < 4; r++) {
            int row = rowBase + r;
            if (row < N_NODES) {
                g_h[row * D_OUT + d] = h[r][0];
                g_h[row * D_OUT + d + 32] = h[r][1];
                s0 += h[r][0]; q0 += h[r][0] * h[r][0];
                s1 += h[r][1]; q1 += h[r][1] * h[r][1];
            }
        }
        __syncwarp();
    }

    atomicAdd(&bsum[d], s0);      atomicAdd(&bsq[d], q0);
    atomicAdd(&bsum[d + 32], s1); atomicAdd(&bsq[d + 32], q1);
    __syncthreads();
    if (tid < D_OUT) {
        atomicAdd(&g_sum[tid], bsum[tid]);
        atomicAdd(&g_sumsq[tid], bsq[tid]);
    }
}

// ---------------- kernel 4: finalize BN params ----------------
__global__ void bn_kernel(const float* __restrict__ gamma,
                          const float* __restrict__ beta) {
    int d = threadIdx.x;
    float n = (float)N_NODES;
    float mean = g_sum[d] / n;
    float var = g_sumsq[d] / n - mean * mean;
    float rstd = rsqrtf(var + BN_EPS);
    float sc = gamma[d] * rstd;
    g_scale[d] = sc;
    g_shift[d] = beta[d] - mean * sc;
}

// ---------------- kernel 5: out = relu(h*scale+shift) @ W2 + b2 ----------------
__global__ void node_out_kernel(const float* __restrict__ W2,
                                const float* __restrict__ b2,
                                float* __restrict__ out) {
    __shared__ __align__(16) float W2s[D_OUT * D_OUT];
    __shared__ __align__(16) float rs[8][4][D_OUT];
    __shared__ __align__(16) float scs[D_OUT];
    __shared__ __align__(16) float shs[D_OUT];
    __shared__ float b2s[D_OUT];

    int tid = threadIdx.x;
    for (int i = tid; i < D_OUT * D_OUT; i += 256) W2s[i] = W2[i];
    if (tid < D_OUT) { scs[tid] = g_scale[tid]; shs[tid] = g_shift[tid]; b2s[tid] = b2[tid]; }
    __syncthreads();

    int warp = tid >> 5, lane = tid & 31;
    int d = lane;

    int nGroups = (N_NODES + 31) / 32;
    for (int g = blockIdx.x; g < nGroups; g += gridDim.x) {
        int rowBase = g * 32 + warp * 4;
        #pragma unroll
        for (int r = 0; r < 4; r++) {
            int row = rowBase + r;
            if (row < N_NODES && lane < 16) {
                float4 hv = ((const float4*)g_h)[row * 16 + lane];
                float4 sc = ((const float4*)scs)[lane];
                float4 sh = ((const float4*)shs)[lane];
                float4 v;
                v.x = fmaxf(0.f, hv.x * sc.x + sh.x);
                v.y = fmaxf(0.f, hv.y * sc.y + sh.y);
                v.z = fmaxf(0.f, hv.z * sc.z + sh.z);
                v.w = fmaxf(0.f, hv.w * sc.w + sh.w);
                ((float4*)&rs[warp][r][0])[lane] = v;
            }
        }
        __syncwarp();

        float y[4][2];
        #pragma unroll
        for (int r = 0; r < 4; r++) { y[r][0] = b2s[d]; y[r][1] = b2s[d + 32]; }
        #pragma unroll 8
        for (int k = 0; k < D_OUT; k++) {
            float w0 = W2s[k * D_OUT + d];
            float w1 = W2s[k * D_OUT + d + 32];
            #pragma unroll
            for (int r = 0; r < 4; r++) {
                float a = rs[warp][r][k];
                y[r][0] += a * w0; y[r][1] += a * w1;
            }
        }
        #pragma unroll
        for (int r = 0; r < 4; r++) {
            int row = rowBase + r;
            if (row < N_NODES) {
                out[row * D_OUT + d] = y[r][0];
                out[row * D_OUT + d + 32] = y[r][1];
            }
        }
        __syncwarp();
    }
}

// ---------------- launch ----------------
extern "C" void kernel_launch(void* const* d_in, const int* in_sizes, int n_in,
                              void* d_out, int out_size) {
    const float* x        = (const float*)d_in[0];
    const int* ei         = (const int*)d_in[1];
    const float* ea       = (const float*)d_in[2];
    const float* We       = (const float*)d_in[3];
    const float* be       = (const float*)d_in[4];
    const float* W1       = (const float*)d_in[5];
    const float* b1       = (const float*)d_in[6];
    const float* gamma    = (const float*)d_in[7];
    const float* beta     = (const float*)d_in[8];
    const float* W2       = (const float*)d_in[9];
    const float* b2       = (const float*)d_in[10];
    float* out            = (float*)d_out;

    zero_kernel<<<2048, 256>>>();
    prep_kernel<<<1, 256>>>(We, be, W1);

    // 2 edges per warp, 8 warps per block
    int nWarps = (N_EDGES + 1) / 2;
    int nBlocks = (nWarps + 7) / 8;
    edge_kernel<<<nBlocks, 256>>>((const float4*)x, ei, (const float4*)ea);

    node_h_kernel<<<592, 256>>>(x, W1, b1);
    bn_kernel<<<1, 64>>>(gamma, beta);
    node_out_kernel<<<592, 256>>>(W2, b2, out);
}